// round 4
// baseline (speedup 1.0000x reference)
#include <cuda_runtime.h>
#include <math.h>

#define B_  4
#define S_  2048
#define D_  1024
#define H_  16
#define DK_ 64
#define MTOT (B_*S_)   // 8192

// Scratch: Q, K, V projections and attention context (allocation-free rule -> device globals)
__device__ float g_Q[(size_t)MTOT * D_];
__device__ float g_K[(size_t)MTOT * D_];
__device__ float g_V[(size_t)MTOT * D_];
__device__ float g_C[(size_t)MTOT * D_];

// ---------------------------------------------------------------------------
// GEMM: Y = X @ W^T   (X: [8192,1024] row-major, W: [1024,1024] row-major over K)
// 128x128 block tile, K-tile 16, 256 threads, 8x8 microtile.
// 2-stage smem double buffering: prefetch gmem->regs during compute, one
// __syncthreads per K-tile. gridDim.z selects (W,Y) pair -> one launch = Q,K,V.
// ---------------------------------------------------------------------------
__global__ __launch_bounds__(256, 2)
void gemm_nt_kernel(const float* __restrict__ X,
                    const float* __restrict__ W0, const float* __restrict__ W1,
                    const float* __restrict__ W2,
                    float* __restrict__ Y0, float* __restrict__ Y1, float* __restrict__ Y2)
{
    const float* W = (blockIdx.z == 0) ? W0 : (blockIdx.z == 1) ? W1 : W2;
    float*       Y = (blockIdx.z == 0) ? Y0 : (blockIdx.z == 1) ? Y1 : Y2;

    __shared__ float As[2][16][132];   // [stage][k][m], padded
    __shared__ float Bs[2][16][132];   // [stage][k][n], padded

    const int tid = threadIdx.x;
    const int tx  = tid & 15;       // n microtile
    const int ty  = tid >> 4;       // m microtile
    const int m0  = blockIdx.y * 128;
    const int n0  = blockIdx.x * 128;

    // per-thread gmem load coords: 512 float4 loads per tile per matrix,
    // thread handles 2 (l = 0,1): row = (tid + 256*l)>>2, kq = ((tid+256*l)&3)*4
    const int row0 = tid >> 2;
    const int kq0  = (tid & 3) * 4;
    const int row1 = (tid + 256) >> 2;
    const int kq1  = kq0;              // (idx&3) identical for +256

    float acc[8][8];
#pragma unroll
    for (int i = 0; i < 8; i++)
#pragma unroll
        for (int j = 0; j < 8; j++) acc[i][j] = 0.f;

    // prologue: load K-tile 0 into stage 0
    float4 xa0 = *(const float4*)&X[(size_t)(m0 + row0) * 1024 + kq0];
    float4 xa1 = *(const float4*)&X[(size_t)(m0 + row1) * 1024 + kq1];
    float4 wa0 = *(const float4*)&W[(size_t)(n0 + row0) * 1024 + kq0];
    float4 wa1 = *(const float4*)&W[(size_t)(n0 + row1) * 1024 + kq1];
    As[0][kq0 + 0][row0] = xa0.x; As[0][kq0 + 1][row0] = xa0.y;
    As[0][kq0 + 2][row0] = xa0.z; As[0][kq0 + 3][row0] = xa0.w;
    As[0][kq1 + 0][row1] = xa1.x; As[0][kq1 + 1][row1] = xa1.y;
    As[0][kq1 + 2][row1] = xa1.z; As[0][kq1 + 3][row1] = xa1.w;
    Bs[0][kq0 + 0][row0] = wa0.x; Bs[0][kq0 + 1][row0] = wa0.y;
    Bs[0][kq0 + 2][row0] = wa0.z; Bs[0][kq0 + 3][row0] = wa0.w;
    Bs[0][kq1 + 0][row1] = wa1.x; Bs[0][kq1 + 1][row1] = wa1.y;
    Bs[0][kq1 + 2][row1] = wa1.z; Bs[0][kq1 + 3][row1] = wa1.w;
    __syncthreads();

    for (int kt = 0; kt < 64; kt++) {
        const int cur = kt & 1;
        const int nxt = cur ^ 1;

        // issue gmem loads for next tile before compute (latency overlap)
        if (kt + 1 < 64) {
            int k0 = (kt + 1) * 16;
            xa0 = *(const float4*)&X[(size_t)(m0 + row0) * 1024 + k0 + kq0];
            xa1 = *(const float4*)&X[(size_t)(m0 + row1) * 1024 + k0 + kq1];
            wa0 = *(const float4*)&W[(size_t)(n0 + row0) * 1024 + k0 + kq0];
            wa1 = *(const float4*)&W[(size_t)(n0 + row1) * 1024 + k0 + kq1];
        }

#pragma unroll
        for (int k = 0; k < 16; k++) {
            float a[8], b[8];
            *(float4*)&a[0] = *(const float4*)&As[cur][k][ty * 8];
            *(float4*)&a[4] = *(const float4*)&As[cur][k][ty * 8 + 4];
            *(float4*)&b[0] = *(const float4*)&Bs[cur][k][tx * 8];
            *(float4*)&b[4] = *(const float4*)&Bs[cur][k][tx * 8 + 4];
#pragma unroll
            for (int i = 0; i < 8; i++)
#pragma unroll
                for (int j = 0; j < 8; j++)
                    acc[i][j] += a[i] * b[j];
        }

        if (kt + 1 < 64) {
            As[nxt][kq0 + 0][row0] = xa0.x; As[nxt][kq0 + 1][row0] = xa0.y;
            As[nxt][kq0 + 2][row0] = xa0.z; As[nxt][kq0 + 3][row0] = xa0.w;
            As[nxt][kq1 + 0][row1] = xa1.x; As[nxt][kq1 + 1][row1] = xa1.y;
            As[nxt][kq1 + 2][row1] = xa1.z; As[nxt][kq1 + 3][row1] = xa1.w;
            Bs[nxt][kq0 + 0][row0] = wa0.x; Bs[nxt][kq0 + 1][row0] = wa0.y;
            Bs[nxt][kq0 + 2][row0] = wa0.z; Bs[nxt][kq0 + 3][row0] = wa0.w;
            Bs[nxt][kq1 + 0][row1] = wa1.x; Bs[nxt][kq1 + 1][row1] = wa1.y;
            Bs[nxt][kq1 + 2][row1] = wa1.z; Bs[nxt][kq1 + 3][row1] = wa1.w;
        }
        __syncthreads();
    }

#pragma unroll
    for (int i = 0; i < 8; i++) {
        size_t r = (size_t)(m0 + ty * 8 + i) * 1024 + n0 + tx * 8;
        float4 v0 = make_float4(acc[i][0], acc[i][1], acc[i][2], acc[i][3]);
        float4 v1 = make_float4(acc[i][4], acc[i][5], acc[i][6], acc[i][7]);
        *(float4*)&Y[r]     = v0;
        *(float4*)&Y[r + 4] = v1;
    }
}

// ---------------------------------------------------------------------------
// Flash attention: one CTA per (q-tile of 64, head, batch). 256 threads.
// Scores tile 64x64 (4x4 per thread), online softmax, PV accumulate.
// Smem: Qs[64][68] | KP[64][68] (K tile, then rewritten with P) | Vs[64][68]
// ---------------------------------------------------------------------------
#define LDA 68
#define ATTN_SMEM (3 * 64 * LDA * (int)sizeof(float))   // 52224 bytes

__global__ __launch_bounds__(256)
void attn_kernel(const float* __restrict__ Q, const float* __restrict__ K,
                 const float* __restrict__ V, float* __restrict__ C)
{
    extern __shared__ float sm[];
    float* Qs = sm;
    float* KP = sm + 64 * LDA;
    float* Vs = sm + 2 * 64 * LDA;

    const int tid = threadIdx.x;
    const int tx  = tid & 15;   // 16-lane group (k-cols in QK^T, d-cols in PV)
    const int ty  = tid >> 4;   // q-rows group
    const int q0  = blockIdx.x * 64;
    const int h   = blockIdx.y;
    const int b   = blockIdx.z;
    const size_t base = ((size_t)b * S_) * D_ + (size_t)h * DK_;  // + s*D + d
    const float scale = 0.125f;  // 1/sqrt(64)

    // Load Q tile, fold in softmax scale
#pragma unroll
    for (int l = 0; l < 4; l++) {
        int idx = tid + l * 256;
        int row = idx >> 4, c = (idx & 15) * 4;
        float4 qv = *(const float4*)&Q[base + (size_t)(q0 + row) * D_ + c];
        qv.x *= scale; qv.y *= scale; qv.z *= scale; qv.w *= scale;
        *(float4*)&Qs[row * LDA + c] = qv;
    }

    float m_i[4], l_i[4], o[4][4];
#pragma unroll
    for (int i = 0; i < 4; i++) {
        m_i[i] = -INFINITY; l_i[i] = 0.f;
#pragma unroll
        for (int j = 0; j < 4; j++) o[i][j] = 0.f;
    }

    for (int ks = 0; ks < S_; ks += 64) {
        __syncthreads();   // protect KP/Vs from previous iteration readers
#pragma unroll
        for (int l = 0; l < 4; l++) {
            int idx = tid + l * 256;
            int row = idx >> 4, c = (idx & 15) * 4;
            *(float4*)&KP[row * LDA + c] = *(const float4*)&K[base + (size_t)(ks + row) * D_ + c];
            *(float4*)&Vs[row * LDA + c] = *(const float4*)&V[base + (size_t)(ks + row) * D_ + c];
        }
        __syncthreads();

        // s = (Q*scale) @ K^T   (4x4 per thread)
        float s4[4][4];
#pragma unroll
        for (int i = 0; i < 4; i++)
#pragma unroll
            for (int j = 0; j < 4; j++) s4[i][j] = 0.f;

        for (int d = 0; d < 64; d += 4) {
            float4 qv[4], kv[4];
#pragma unroll
            for (int i = 0; i < 4; i++) qv[i] = *(const float4*)&Qs[(ty * 4 + i) * LDA + d];
#pragma unroll
            for (int j = 0; j < 4; j++) kv[j] = *(const float4*)&KP[(tx * 4 + j) * LDA + d];
#pragma unroll
            for (int i = 0; i < 4; i++)
#pragma unroll
                for (int j = 0; j < 4; j++)
                    s4[i][j] += qv[i].x * kv[j].x + qv[i].y * kv[j].y
                              + qv[i].z * kv[j].z + qv[i].w * kv[j].w;
        }

        // Online softmax per q-row (reduce across the 16 tx lanes)
#pragma unroll
        for (int i = 0; i < 4; i++) {
            float r = fmaxf(fmaxf(s4[i][0], s4[i][1]), fmaxf(s4[i][2], s4[i][3]));
#pragma unroll
            for (int msk = 1; msk < 16; msk <<= 1)
                r = fmaxf(r, __shfl_xor_sync(0xffffffffu, r, msk));
            float mnew = fmaxf(m_i[i], r);
            float f    = __expf(m_i[i] - mnew);   // 0 when m_i == -inf
            m_i[i] = mnew;
            float rs = 0.f;
#pragma unroll
            for (int j = 0; j < 4; j++) {
                s4[i][j] = __expf(s4[i][j] - mnew);
                rs += s4[i][j];
            }
#pragma unroll
            for (int msk = 1; msk < 16; msk <<= 1)
                rs += __shfl_xor_sync(0xffffffffu, rs, msk);
            l_i[i] = l_i[i] * f + rs;
#pragma unroll
            for (int j = 0; j < 4; j++) o[i][j] *= f;
        }

        __syncthreads();   // all done reading K tile
#pragma unroll
        for (int i = 0; i < 4; i++)
            *(float4*)&KP[(ty * 4 + i) * LDA + tx * 4] =
                make_float4(s4[i][0], s4[i][1], s4[i][2], s4[i][3]);
        __syncthreads();

        // O += P @ V
        for (int kk = 0; kk < 64; kk += 4) {
            float4 p4[4], v4[4];
#pragma unroll
            for (int i = 0; i < 4; i++) p4[i] = *(const float4*)&KP[(ty * 4 + i) * LDA + kk];
#pragma unroll
            for (int j = 0; j < 4; j++) v4[j] = *(const float4*)&Vs[(kk + j) * LDA + tx * 4];
#pragma unroll
            for (int i = 0; i < 4; i++) {
                o[i][0] += p4[i].x * v4[0].x + p4[i].y * v4[1].x + p4[i].z * v4[2].x + p4[i].w * v4[3].x;
                o[i][1] += p4[i].x * v4[0].y + p4[i].y * v4[1].y + p4[i].z * v4[2].y + p4[i].w * v4[3].y;
                o[i][2] += p4[i].x * v4[0].z + p4[i].y * v4[1].z + p4[i].z * v4[2].z + p4[i].w * v4[3].z;
                o[i][3] += p4[i].x * v4[0].w + p4[i].y * v4[1].w + p4[i].z * v4[2].w + p4[i].w * v4[3].w;
            }
        }
    }

    // epilogue: normalize, write ctx[b, q, h*64 + d]
#pragma unroll
    for (int i = 0; i < 4; i++) {
        float inv = 1.f / l_i[i];
        float4 r = make_float4(o[i][0] * inv, o[i][1] * inv, o[i][2] * inv, o[i][3] * inv);
        *(float4*)&C[base + (size_t)(q0 + ty * 4 + i) * D_ + tx * 4] = r;
    }
}

// ---------------------------------------------------------------------------
extern "C" void kernel_launch(void* const* d_in, const int* in_sizes, int n_in,
                              void* d_out, int out_size)
{
    const float* X  = (const float*)d_in[0];
    const float* Wq = (const float*)d_in[1];
    const float* Wk = (const float*)d_in[2];
    const float* Wv = (const float*)d_in[3];
    const float* Wo = (const float*)d_in[4];
    float* out = (float*)d_out;

    float *Q, *K, *V, *C;
    cudaGetSymbolAddress((void**)&Q, g_Q);
    cudaGetSymbolAddress((void**)&K, g_K);
    cudaGetSymbolAddress((void**)&V, g_V);
    cudaGetSymbolAddress((void**)&C, g_C);

    cudaFuncSetAttribute(attn_kernel, cudaFuncAttributeMaxDynamicSharedMemorySize, ATTN_SMEM);

    // 1) fused QKV projections
    dim3 gqkv(1024 / 128, MTOT / 128, 3);
    gemm_nt_kernel<<<gqkv, 256>>>(X, Wq, Wk, Wv, Q, K, V);

    // 2) attention
    dim3 gattn(S_ / 64, H_, B_);
    attn_kernel<<<gattn, 256, ATTN_SMEM>>>(Q, K, V, C);

    // 3) output projection
    dim3 go(1024 / 128, MTOT / 128, 1);
    gemm_nt_kernel<<<go, 256>>>(C, Wo, Wo, Wo, out, out, out);
}

// round 6
// speedup vs baseline: 1.1998x; 1.1998x over previous
#include <cuda_runtime.h>
#include <cuda_bf16.h>
#include <math.h>
#include <cstdint>

#define B_  4
#define S_  2048
#define D_  1024
#define H_  16
#define DK_ 64
#define MTOT (B_*S_)   // 8192

// ---------------------------------------------------------------------------
// Device-global scratch (allocation-free rule)
// ---------------------------------------------------------------------------
__device__ float g_Q[(size_t)MTOT * D_];
__device__ float g_K[(size_t)MTOT * D_];
__device__ float g_V[(size_t)MTOT * D_];
__device__ float g_C[(size_t)MTOT * D_];
__device__ __nv_bfloat16 g_Ah[(size_t)MTOT * D_];   // hi(X) then hi(C)
__device__ __nv_bfloat16 g_Al[(size_t)MTOT * D_];   // lo(X) then lo(C)
__device__ __nv_bfloat16 g_Wh[4 * 1024 * 1024];     // hi(Wq,Wk,Wv,Wo)
__device__ __nv_bfloat16 g_Wl[4 * 1024 * 1024];     // lo(...)

__device__ __forceinline__ uint32_t smem_to_u32(const void* p) {
    uint32_t a;
    asm("{ .reg .u64 t; cvta.to.shared.u64 t, %1; cvt.u32.u64 %0, t; }" : "=r"(a) : "l"(p));
    return a;
}

// family-common tensor-core primitives (sm_80+ PTX; valid on sm_103 base target)
__device__ __forceinline__ void ldsm4(uint32_t* r, uint32_t addr) {
    asm volatile("ldmatrix.sync.aligned.m8n8.x4.shared.b16 {%0,%1,%2,%3}, [%4];"
                 : "=r"(r[0]), "=r"(r[1]), "=r"(r[2]), "=r"(r[3]) : "r"(addr));
}
__device__ __forceinline__ void mma_bf16(float* d, const uint32_t* a, const uint32_t* b) {
    asm volatile("mma.sync.aligned.m16n8k16.row.col.f32.bf16.bf16.f32 "
                 "{%0,%1,%2,%3}, {%4,%5,%6,%7}, {%8,%9}, {%0,%1,%2,%3};"
                 : "+f"(d[0]), "+f"(d[1]), "+f"(d[2]), "+f"(d[3])
                 : "r"(a[0]), "r"(a[1]), "r"(a[2]), "r"(a[3]), "r"(b[0]), "r"(b[1]));
}

// ---------------------------------------------------------------------------
// fp32 -> (hi, lo) bf16 split
// ---------------------------------------------------------------------------
__global__ void cvt_hilo(const float* __restrict__ x, __nv_bfloat16* __restrict__ hi,
                         __nv_bfloat16* __restrict__ lo, int n) {
    int i = blockIdx.x * 256 + threadIdx.x;
    if (i < n) {
        float v = x[i];
        __nv_bfloat16 h = __float2bfloat16(v);
        hi[i] = h;
        lo[i] = __float2bfloat16(v - __bfloat162float(h));
    }
}

// ---------------------------------------------------------------------------
// bf16x3 GEMM on mma.sync: Y[M,N] = X @ W^T (X:[M,1024], W:[N,1024], K-major)
// CTA 128x128, 512 threads (16 warps, 4x4 grid, warp tile 32x32), K-chunk 32,
// 2-stage smem double buffer with register prefetch.
// Smem tile rows padded to 40 bf16 (80B) -> conflict-free ldmatrix.
// ---------------------------------------------------------------------------
#define KC        32
#define TSTRIDE   40                        // bf16 per smem row
#define TILE_B    (128 * TSTRIDE * 2)       // 10240 bytes per tile
#define STAGE_B   (4 * TILE_B)              // Ah,Al,Bh,Bl = 40960
#define GEMM_SMEM (2 * STAGE_B)             // 81920

__global__ __launch_bounds__(512, 1)
void gemm_tc_kernel(const __nv_bfloat16* __restrict__ Ah, const __nv_bfloat16* __restrict__ Al,
                    const __nv_bfloat16* __restrict__ B0h, const __nv_bfloat16* __restrict__ B0l,
                    const __nv_bfloat16* __restrict__ B1h, const __nv_bfloat16* __restrict__ B1l,
                    const __nv_bfloat16* __restrict__ B2h, const __nv_bfloat16* __restrict__ B2l,
                    float* __restrict__ Y0, float* __restrict__ Y1, float* __restrict__ Y2)
{
    const __nv_bfloat16* Bh = (blockIdx.z == 0) ? B0h : (blockIdx.z == 1) ? B1h : B2h;
    const __nv_bfloat16* Bl = (blockIdx.z == 0) ? B0l : (blockIdx.z == 1) ? B1l : B2l;
    float*               Y  = (blockIdx.z == 0) ? Y0  : (blockIdx.z == 1) ? Y1  : Y2;

    extern __shared__ char smem[];
    const uint32_t sb = smem_to_u32(smem);
    const int tid = threadIdx.x;
    const int wid = tid >> 5;
    const int lid = tid & 31;
    const int wm  = wid >> 2;     // 0..3 (m)
    const int wn  = wid & 3;      // 0..3 (n)
    const int m0  = blockIdx.y * 128;
    const int n0  = blockIdx.x * 128;

    // gmem->smem: one float4 (8 bf16) per tile per thread per chunk
    const int grow = tid >> 2;            // 0..127
    const int gcg  = (tid & 3) * 8;       // bf16 col within chunk
    const uint32_t s_off = (uint32_t)grow * (TSTRIDE * 2) + (uint32_t)(tid & 3) * 16;
    const size_t gA = (size_t)(m0 + grow) * 1024 + gcg;   // + chunk*32
    const size_t gB = (size_t)(n0 + grow) * 1024 + gcg;

    // ldmatrix lane address components (bytes, relative to tile base)
    const uint32_t aRow = (uint32_t)(wm * 32 + (lid & 15)) * (TSTRIDE * 2) + ((lid & 16) ? 16u : 0u);
    const uint32_t bRow = (uint32_t)(wn * 32 + (lid & 7) + ((lid & 16) ? 8 : 0)) * (TSTRIDE * 2)
                          + ((lid & 8) ? 16u : 0u);

    float acc[2][4][4];
#pragma unroll
    for (int mb = 0; mb < 2; mb++)
#pragma unroll
        for (int nb = 0; nb < 4; nb++)
#pragma unroll
            for (int q = 0; q < 4; q++) acc[mb][nb][q] = 0.f;

    // prologue: chunk 0 -> stage 0
    {
        *(float4*)(smem + 0 * TILE_B + s_off) = *(const float4*)(Ah + gA);
        *(float4*)(smem + 1 * TILE_B + s_off) = *(const float4*)(Al + gA);
        *(float4*)(smem + 2 * TILE_B + s_off) = *(const float4*)(Bh + gB);
        *(float4*)(smem + 3 * TILE_B + s_off) = *(const float4*)(Bl + gB);
    }
    __syncthreads();

    for (int c = 0; c < 32; c++) {
        const uint32_t st = sb + (uint32_t)(c & 1) * STAGE_B;

        // prefetch next chunk to regs
        float4 pAh, pAl, pBh, pBl;
        if (c + 1 < 32) {
            const size_t ko = (size_t)(c + 1) * KC;
            pAh = *(const float4*)(Ah + gA + ko);
            pAl = *(const float4*)(Al + gA + ko);
            pBh = *(const float4*)(Bh + gB + ko);
            pBl = *(const float4*)(Bl + gB + ko);
        }

#pragma unroll
        for (int ks = 0; ks < 2; ks++) {
            const uint32_t kb = (uint32_t)ks * 32;   // byte offset of k16 step
            uint32_t fa[2][4], fb_h[2][4], fb_l[2][4], fal[2][4];
#pragma unroll
            for (int mb = 0; mb < 2; mb++)
                ldsm4(fa[mb], st + 0 * TILE_B + aRow + (uint32_t)mb * (16 * TSTRIDE * 2) + kb);
#pragma unroll
            for (int nb = 0; nb < 2; nb++) {
                ldsm4(fb_h[nb], st + 2 * TILE_B + bRow + (uint32_t)nb * (16 * TSTRIDE * 2) + kb);
                ldsm4(fb_l[nb], st + 3 * TILE_B + bRow + (uint32_t)nb * (16 * TSTRIDE * 2) + kb);
            }
#pragma unroll
            for (int mb = 0; mb < 2; mb++)
#pragma unroll
                for (int nb = 0; nb < 4; nb++) {
                    mma_bf16(acc[mb][nb], fa[mb], &fb_h[nb >> 1][(nb & 1) * 2]);
                    mma_bf16(acc[mb][nb], fa[mb], &fb_l[nb >> 1][(nb & 1) * 2]);
                }
#pragma unroll
            for (int mb = 0; mb < 2; mb++)
                ldsm4(fal[mb], st + 1 * TILE_B + aRow + (uint32_t)mb * (16 * TSTRIDE * 2) + kb);
#pragma unroll
            for (int mb = 0; mb < 2; mb++)
#pragma unroll
                for (int nb = 0; nb < 4; nb++)
                    mma_bf16(acc[mb][nb], fal[mb], &fb_h[nb >> 1][(nb & 1) * 2]);
        }

        // store prefetched chunk to the other stage
        if (c + 1 < 32) {
            char* sn = smem + ((c + 1) & 1) * STAGE_B;
            *(float4*)(sn + 0 * TILE_B + s_off) = pAh;
            *(float4*)(sn + 1 * TILE_B + s_off) = pAl;
            *(float4*)(sn + 2 * TILE_B + s_off) = pBh;
            *(float4*)(sn + 3 * TILE_B + s_off) = pBl;
        }
        __syncthreads();
    }

    // epilogue: C frag (r,2c),(r,2c+1) / (r+8,...) -> float2 stores
    const int rr = lid >> 2;
    const int cc = (lid & 3) * 2;
#pragma unroll
    for (int mb = 0; mb < 2; mb++) {
        const int row = m0 + wm * 32 + mb * 16 + rr;
#pragma unroll
        for (int nb = 0; nb < 4; nb++) {
            const int col = n0 + wn * 32 + nb * 8 + cc;
            *(float2*)&Y[(size_t)row * 1024 + col]       = make_float2(acc[mb][nb][0], acc[mb][nb][1]);
            *(float2*)&Y[(size_t)(row + 8) * 1024 + col] = make_float2(acc[mb][nb][2], acc[mb][nb][3]);
        }
    }
}

// ---------------------------------------------------------------------------
// Flash attention (unchanged, known-correct fp32 SIMT from R4)
// ---------------------------------------------------------------------------
#define LDA 68
#define ATTN_SMEM (3 * 64 * LDA * (int)sizeof(float))   // 52224 bytes

__global__ __launch_bounds__(256)
void attn_kernel(const float* __restrict__ Q, const float* __restrict__ K,
                 const float* __restrict__ V, float* __restrict__ C)
{
    extern __shared__ float sm[];
    float* Qs = sm;
    float* KP = sm + 64 * LDA;
    float* Vs = sm + 2 * 64 * LDA;

    const int tid = threadIdx.x;
    const int tx  = tid & 15;
    const int ty  = tid >> 4;
    const int q0  = blockIdx.x * 64;
    const int h   = blockIdx.y;
    const int b   = blockIdx.z;
    const size_t base = ((size_t)b * S_) * D_ + (size_t)h * DK_;
    const float scale = 0.125f;

#pragma unroll
    for (int l = 0; l < 4; l++) {
        int idx = tid + l * 256;
        int row = idx >> 4, c = (idx & 15) * 4;
        float4 qv = *(const float4*)&Q[base + (size_t)(q0 + row) * D_ + c];
        qv.x *= scale; qv.y *= scale; qv.z *= scale; qv.w *= scale;
        *(float4*)&Qs[row * LDA + c] = qv;
    }

    float m_i[4], l_i[4], o[4][4];
#pragma unroll
    for (int i = 0; i < 4; i++) {
        m_i[i] = -INFINITY; l_i[i] = 0.f;
#pragma unroll
        for (int j = 0; j < 4; j++) o[i][j] = 0.f;
    }

    for (int ks = 0; ks < S_; ks += 64) {
        __syncthreads();
#pragma unroll
        for (int l = 0; l < 4; l++) {
            int idx = tid + l * 256;
            int row = idx >> 4, c = (idx & 15) * 4;
            *(float4*)&KP[row * LDA + c] = *(const float4*)&K[base + (size_t)(ks + row) * D_ + c];
            *(float4*)&Vs[row * LDA + c] = *(const float4*)&V[base + (size_t)(ks + row) * D_ + c];
        }
        __syncthreads();

        float s4[4][4];
#pragma unroll
        for (int i = 0; i < 4; i++)
#pragma unroll
            for (int j = 0; j < 4; j++) s4[i][j] = 0.f;

        for (int d = 0; d < 64; d += 4) {
            float4 qv[4], kv[4];
#pragma unroll
            for (int i = 0; i < 4; i++) qv[i] = *(const float4*)&Qs[(ty * 4 + i) * LDA + d];
#pragma unroll
            for (int j = 0; j < 4; j++) kv[j] = *(const float4*)&KP[(tx * 4 + j) * LDA + d];
#pragma unroll
            for (int i = 0; i < 4; i++)
#pragma unroll
                for (int j = 0; j < 4; j++)
                    s4[i][j] += qv[i].x * kv[j].x + qv[i].y * kv[j].y
                              + qv[i].z * kv[j].z + qv[i].w * kv[j].w;
        }

#pragma unroll
        for (int i = 0; i < 4; i++) {
            float r = fmaxf(fmaxf(s4[i][0], s4[i][1]), fmaxf(s4[i][2], s4[i][3]));
#pragma unroll
            for (int msk = 1; msk < 16; msk <<= 1)
                r = fmaxf(r, __shfl_xor_sync(0xffffffffu, r, msk));
            float mnew = fmaxf(m_i[i], r);
            float f    = __expf(m_i[i] - mnew);
            m_i[i] = mnew;
            float rs = 0.f;
#pragma unroll
            for (int j = 0; j < 4; j++) {
                s4[i][j] = __expf(s4[i][j] - mnew);
                rs += s4[i][j];
            }
#pragma unroll
            for (int msk = 1; msk < 16; msk <<= 1)
                rs += __shfl_xor_sync(0xffffffffu, rs, msk);
            l_i[i] = l_i[i] * f + rs;
#pragma unroll
            for (int j = 0; j < 4; j++) o[i][j] *= f;
        }

        __syncthreads();
#pragma unroll
        for (int i = 0; i < 4; i++)
            *(float4*)&KP[(ty * 4 + i) * LDA + tx * 4] =
                make_float4(s4[i][0], s4[i][1], s4[i][2], s4[i][3]);
        __syncthreads();

        for (int kk = 0; kk < 64; kk += 4) {
            float4 p4[4], v4[4];
#pragma unroll
            for (int i = 0; i < 4; i++) p4[i] = *(const float4*)&KP[(ty * 4 + i) * LDA + kk];
#pragma unroll
            for (int j = 0; j < 4; j++) v4[j] = *(const float4*)&Vs[(kk + j) * LDA + tx * 4];
#pragma unroll
            for (int i = 0; i < 4; i++) {
                o[i][0] += p4[i].x * v4[0].x + p4[i].y * v4[1].x + p4[i].z * v4[2].x + p4[i].w * v4[3].x;
                o[i][1] += p4[i].x * v4[0].y + p4[i].y * v4[1].y + p4[i].z * v4[2].y + p4[i].w * v4[3].y;
                o[i][2] += p4[i].x * v4[0].z + p4[i].y * v4[1].z + p4[i].z * v4[2].z + p4[i].w * v4[3].z;
                o[i][3] += p4[i].x * v4[0].w + p4[i].y * v4[1].w + p4[i].z * v4[2].w + p4[i].w * v4[3].w;
            }
        }
    }

#pragma unroll
    for (int i = 0; i < 4; i++) {
        float inv = 1.f / l_i[i];
        float4 r = make_float4(o[i][0] * inv, o[i][1] * inv, o[i][2] * inv, o[i][3] * inv);
        *(float4*)&C[base + (size_t)(q0 + ty * 4 + i) * D_ + tx * 4] = r;
    }
}

// ---------------------------------------------------------------------------
extern "C" void kernel_launch(void* const* d_in, const int* in_sizes, int n_in,
                              void* d_out, int out_size)
{
    const float* X  = (const float*)d_in[0];
    const float* Wq = (const float*)d_in[1];
    const float* Wk = (const float*)d_in[2];
    const float* Wv = (const float*)d_in[3];
    const float* Wo = (const float*)d_in[4];
    float* out = (float*)d_out;

    float *Q, *K, *V, *C;
    __nv_bfloat16 *Ah, *Al, *Wh, *Wl;
    cudaGetSymbolAddress((void**)&Q,  g_Q);
    cudaGetSymbolAddress((void**)&K,  g_K);
    cudaGetSymbolAddress((void**)&V,  g_V);
    cudaGetSymbolAddress((void**)&C,  g_C);
    cudaGetSymbolAddress((void**)&Ah, g_Ah);
    cudaGetSymbolAddress((void**)&Al, g_Al);
    cudaGetSymbolAddress((void**)&Wh, g_Wh);
    cudaGetSymbolAddress((void**)&Wl, g_Wl);

    cudaFuncSetAttribute(attn_kernel,    cudaFuncAttributeMaxDynamicSharedMemorySize, ATTN_SMEM);
    cudaFuncSetAttribute(gemm_tc_kernel, cudaFuncAttributeMaxDynamicSharedMemorySize, GEMM_SMEM);

    const int NX = MTOT * D_;        // 8388608
    const int NW = D_ * D_;          // 1048576

    // 0) hi/lo splits
    cvt_hilo<<<NX / 256, 256>>>(X,  Ah, Al, NX);
    cvt_hilo<<<NW / 256, 256>>>(Wq, Wh + 0 * (size_t)NW, Wl + 0 * (size_t)NW, NW);
    cvt_hilo<<<NW / 256, 256>>>(Wk, Wh + 1 * (size_t)NW, Wl + 1 * (size_t)NW, NW);
    cvt_hilo<<<NW / 256, 256>>>(Wv, Wh + 2 * (size_t)NW, Wl + 2 * (size_t)NW, NW);
    cvt_hilo<<<NW / 256, 256>>>(Wo, Wh + 3 * (size_t)NW, Wl + 3 * (size_t)NW, NW);

    // 1) QKV projections on tensor cores (z selects Wq/Wk/Wv -> Q/K/V)
    dim3 gqkv(1024 / 128, MTOT / 128, 3);
    gemm_tc_kernel<<<gqkv, 512, GEMM_SMEM>>>(
        Ah, Al,
        Wh + 0 * (size_t)NW, Wl + 0 * (size_t)NW,
        Wh + 1 * (size_t)NW, Wl + 1 * (size_t)NW,
        Wh + 2 * (size_t)NW, Wl + 2 * (size_t)NW,
        Q, K, V);

    // 2) attention (fp32 SIMT, unchanged)
    dim3 gattn(S_ / 64, H_, B_);
    attn_kernel<<<gattn, 256, ATTN_SMEM>>>(Q, K, V, C);

    // 3) output projection: split C, then mma.sync GEMM
    cvt_hilo<<<NX / 256, 256>>>(C, Ah, Al, NX);
    dim3 go(1024 / 128, MTOT / 128, 1);
    gemm_tc_kernel<<<go, 512, GEMM_SMEM>>>(
        Ah, Al,
        Wh + 3 * (size_t)NW, Wl + 3 * (size_t)NW,
        Wh + 3 * (size_t)NW, Wl + 3 * (size_t)NW,
        Wh + 3 * (size_t)NW, Wl + 3 * (size_t)NW,
        out, out, out);
}

// round 7
// speedup vs baseline: 3.4262x; 2.8557x over previous
#include <cuda_runtime.h>
#include <cuda_bf16.h>
#include <math.h>
#include <cstdint>

#define B_  4
#define S_  2048
#define D_  1024
#define H_  16
#define DK_ 64
#define MTOT (B_*S_)   // 8192

typedef __nv_bfloat16 bf16;

// ---------------------------------------------------------------------------
// Device-global scratch (allocation-free rule)
// ---------------------------------------------------------------------------
__device__ bf16 g_Ah[(size_t)MTOT * D_];   // hi(X), later hi(ctx)
__device__ bf16 g_Al[(size_t)MTOT * D_];   // lo(X), later lo(ctx)
__device__ bf16 g_Wh[4 * 1024 * 1024];     // hi(Wq,Wk,Wv,Wo)
__device__ bf16 g_Wl[4 * 1024 * 1024];
__device__ bf16 g_Qh[(size_t)MTOT * D_];
__device__ bf16 g_Ql[(size_t)MTOT * D_];
__device__ bf16 g_Kh[(size_t)MTOT * D_];
__device__ bf16 g_Kl[(size_t)MTOT * D_];
__device__ bf16 g_Vh[(size_t)MTOT * D_];
__device__ bf16 g_Vl[(size_t)MTOT * D_];

__device__ __forceinline__ uint32_t smem_to_u32(const void* p) {
    uint32_t a;
    asm("{ .reg .u64 t; cvta.to.shared.u64 t, %1; cvt.u32.u64 %0, t; }" : "=r"(a) : "l"(p));
    return a;
}
__device__ __forceinline__ void ldsm4(uint32_t* r, uint32_t addr) {
    asm volatile("ldmatrix.sync.aligned.m8n8.x4.shared.b16 {%0,%1,%2,%3}, [%4];"
                 : "=r"(r[0]), "=r"(r[1]), "=r"(r[2]), "=r"(r[3]) : "r"(addr));
}
__device__ __forceinline__ void ldsm4t(uint32_t* r, uint32_t addr) {
    asm volatile("ldmatrix.sync.aligned.m8n8.x4.trans.shared.b16 {%0,%1,%2,%3}, [%4];"
                 : "=r"(r[0]), "=r"(r[1]), "=r"(r[2]), "=r"(r[3]) : "r"(addr));
}
__device__ __forceinline__ void mma_bf16(float* d, const uint32_t* a, const uint32_t* b) {
    asm volatile("mma.sync.aligned.m16n8k16.row.col.f32.bf16.bf16.f32 "
                 "{%0,%1,%2,%3}, {%4,%5,%6,%7}, {%8,%9}, {%0,%1,%2,%3};"
                 : "+f"(d[0]), "+f"(d[1]), "+f"(d[2]), "+f"(d[3])
                 : "r"(a[0]), "r"(a[1]), "r"(a[2]), "r"(a[3]), "r"(b[0]), "r"(b[1]));
}
#define CP_ASYNC16(s, g) \
    asm volatile("cp.async.cg.shared.global [%0], [%1], 16;" :: "r"(s), "l"(g))
#define CP_COMMIT() asm volatile("cp.async.commit_group;" ::: "memory")
#define CP_WAIT0()  asm volatile("cp.async.wait_group 0;" ::: "memory")

__device__ __forceinline__ uint32_t pack_bf16(float a, float b) {
    __nv_bfloat162 t = __floats2bfloat162_rn(a, b);   // .x = a (low 16 bits)
    return *(uint32_t*)&t;
}

// ---------------------------------------------------------------------------
// fp32 -> (hi, lo) bf16 split
// ---------------------------------------------------------------------------
__global__ void cvt_hilo(const float* __restrict__ x, bf16* __restrict__ hi,
                         bf16* __restrict__ lo, int n) {
    int i = blockIdx.x * 256 + threadIdx.x;
    if (i < n) {
        float v = x[i];
        bf16 h = __float2bfloat16(v);
        hi[i] = h;
        lo[i] = __float2bfloat16(v - __bfloat162float(h));
    }
}

// ---------------------------------------------------------------------------
// bf16x3 GEMM on mma.sync: Y = X @ W^T. CTA 128x128, 512 thr, K-chunk 32,
// 2-stage double buffer (same mainloop as R6-passing kernel).
// Epilogue: fp32 (Yf) OR hi/lo bf16 split with optional scale (QKV path).
// ---------------------------------------------------------------------------
#define KC        32
#define TSTRIDE   40
#define TILE_B    (128 * TSTRIDE * 2)
#define STAGE_B   (4 * TILE_B)
#define GEMM_SMEM (2 * STAGE_B)             // 81920

__global__ __launch_bounds__(512, 1)
void gemm_tc_kernel(const bf16* __restrict__ Ah, const bf16* __restrict__ Al,
                    const bf16* __restrict__ B0h, const bf16* __restrict__ B0l,
                    const bf16* __restrict__ B1h, const bf16* __restrict__ B1l,
                    const bf16* __restrict__ B2h, const bf16* __restrict__ B2l,
                    bf16* __restrict__ Yh0, bf16* __restrict__ Yl0,
                    bf16* __restrict__ Yh1, bf16* __restrict__ Yl1,
                    bf16* __restrict__ Yh2, bf16* __restrict__ Yl2,
                    float* __restrict__ Yf, float sc0)
{
    const bf16* Bh = (blockIdx.z == 0) ? B0h : (blockIdx.z == 1) ? B1h : B2h;
    const bf16* Bl = (blockIdx.z == 0) ? B0l : (blockIdx.z == 1) ? B1l : B2l;
    bf16* Yh = (blockIdx.z == 0) ? Yh0 : (blockIdx.z == 1) ? Yh1 : Yh2;
    bf16* Yl = (blockIdx.z == 0) ? Yl0 : (blockIdx.z == 1) ? Yl1 : Yl2;
    const float osc = (blockIdx.z == 0) ? sc0 : 1.f;

    extern __shared__ char smem[];
    const uint32_t sb = smem_to_u32(smem);
    const int tid = threadIdx.x;
    const int wid = tid >> 5;
    const int lid = tid & 31;
    const int wm  = wid >> 2;
    const int wn  = wid & 3;
    const int m0  = blockIdx.y * 128;
    const int n0  = blockIdx.x * 128;

    const int grow = tid >> 2;
    const int gcg  = (tid & 3) * 8;
    const uint32_t s_off = (uint32_t)grow * (TSTRIDE * 2) + (uint32_t)(tid & 3) * 16;
    const size_t gA = (size_t)(m0 + grow) * 1024 + gcg;
    const size_t gB = (size_t)(n0 + grow) * 1024 + gcg;

    const uint32_t aRow = (uint32_t)(wm * 32 + (lid & 15)) * (TSTRIDE * 2) + ((lid & 16) ? 16u : 0u);
    const uint32_t bRow = (uint32_t)(wn * 32 + (lid & 7) + ((lid & 16) ? 8 : 0)) * (TSTRIDE * 2)
                          + ((lid & 8) ? 16u : 0u);

    float acc[2][4][4];
#pragma unroll
    for (int mb = 0; mb < 2; mb++)
#pragma unroll
        for (int nb = 0; nb < 4; nb++)
#pragma unroll
            for (int q = 0; q < 4; q++) acc[mb][nb][q] = 0.f;

    *(float4*)(smem + 0 * TILE_B + s_off) = *(const float4*)(Ah + gA);
    *(float4*)(smem + 1 * TILE_B + s_off) = *(const float4*)(Al + gA);
    *(float4*)(smem + 2 * TILE_B + s_off) = *(const float4*)(Bh + gB);
    *(float4*)(smem + 3 * TILE_B + s_off) = *(const float4*)(Bl + gB);
    __syncthreads();

    for (int c = 0; c < 32; c++) {
        const uint32_t st = sb + (uint32_t)(c & 1) * STAGE_B;

        float4 pAh, pAl, pBh, pBl;
        if (c + 1 < 32) {
            const size_t ko = (size_t)(c + 1) * KC;
            pAh = *(const float4*)(Ah + gA + ko);
            pAl = *(const float4*)(Al + gA + ko);
            pBh = *(const float4*)(Bh + gB + ko);
            pBl = *(const float4*)(Bl + gB + ko);
        }

#pragma unroll
        for (int ks = 0; ks < 2; ks++) {
            const uint32_t kb = (uint32_t)ks * 32;
            uint32_t fa[2][4], fb_h[2][4], fb_l[2][4], fal[2][4];
#pragma unroll
            for (int mb = 0; mb < 2; mb++)
                ldsm4(fa[mb], st + 0 * TILE_B + aRow + (uint32_t)mb * (16 * TSTRIDE * 2) + kb);
#pragma unroll
            for (int nb = 0; nb < 2; nb++) {
                ldsm4(fb_h[nb], st + 2 * TILE_B + bRow + (uint32_t)nb * (16 * TSTRIDE * 2) + kb);
                ldsm4(fb_l[nb], st + 3 * TILE_B + bRow + (uint32_t)nb * (16 * TSTRIDE * 2) + kb);
            }
#pragma unroll
            for (int mb = 0; mb < 2; mb++)
#pragma unroll
                for (int nb = 0; nb < 4; nb++) {
                    mma_bf16(acc[mb][nb], fa[mb], &fb_h[nb >> 1][(nb & 1) * 2]);
                    mma_bf16(acc[mb][nb], fa[mb], &fb_l[nb >> 1][(nb & 1) * 2]);
                }
#pragma unroll
            for (int mb = 0; mb < 2; mb++)
                ldsm4(fal[mb], st + 1 * TILE_B + aRow + (uint32_t)mb * (16 * TSTRIDE * 2) + kb);
#pragma unroll
            for (int mb = 0; mb < 2; mb++)
#pragma unroll
                for (int nb = 0; nb < 4; nb++)
                    mma_bf16(acc[mb][nb], fal[mb], &fb_h[nb >> 1][(nb & 1) * 2]);
        }

        if (c + 1 < 32) {
            char* sn = smem + ((c + 1) & 1) * STAGE_B;
            *(float4*)(sn + 0 * TILE_B + s_off) = pAh;
            *(float4*)(sn + 1 * TILE_B + s_off) = pAl;
            *(float4*)(sn + 2 * TILE_B + s_off) = pBh;
            *(float4*)(sn + 3 * TILE_B + s_off) = pBl;
        }
        __syncthreads();
    }

    const int rr = lid >> 2;
    const int cc = (lid & 3) * 2;
    if (Yf) {
#pragma unroll
        for (int mb = 0; mb < 2; mb++) {
            const int row = m0 + wm * 32 + mb * 16 + rr;
#pragma unroll
            for (int nb = 0; nb < 4; nb++) {
                const int col = n0 + wn * 32 + nb * 8 + cc;
                *(float2*)&Yf[(size_t)row * 1024 + col]       = make_float2(acc[mb][nb][0], acc[mb][nb][1]);
                *(float2*)&Yf[(size_t)(row + 8) * 1024 + col] = make_float2(acc[mb][nb][2], acc[mb][nb][3]);
            }
        }
    } else {
#pragma unroll
        for (int mb = 0; mb < 2; mb++) {
            const int row = m0 + wm * 32 + mb * 16 + rr;
#pragma unroll
            for (int nb = 0; nb < 4; nb++) {
                const int col = n0 + wn * 32 + nb * 8 + cc;
#pragma unroll
                for (int half = 0; half < 2; half++) {   // half=0: row, half=1: row+8
                    float v0 = acc[mb][nb][half * 2 + 0] * osc;
                    float v1 = acc[mb][nb][half * 2 + 1] * osc;
                    bf16 h0 = __float2bfloat16(v0), h1 = __float2bfloat16(v1);
                    float l0 = v0 - __bfloat162float(h0), l1 = v1 - __bfloat162float(h1);
                    size_t off = (size_t)(row + half * 8) * 1024 + col;
                    *(uint32_t*)&Yh[off] = pack_bf16(__bfloat162float(h0), __bfloat162float(h1));
                    *(uint32_t*)&Yl[off] = pack_bf16(l0, l1);
                }
            }
        }
    }
}

// ---------------------------------------------------------------------------
// Flash attention on mma.sync bf16x3.
// CTA: 256 thr = 8 warps, each warp 16 q-rows -> 128 q-rows per CTA.
// Key chunk 64, smem stages: {Kh,Kl,Vh,Vl}[64 x 144B] x2, Q hi/lo staged after.
// Softmax online per warp; P split hi/lo in registers; V^T via ldmatrix.trans.
// ---------------------------------------------------------------------------
#define AT_STR   144                       // smem row stride bytes (64 bf16 data + pad)
#define AT_TILE  (64 * AT_STR)             // 9216
#define AT_STAGE (4 * AT_TILE)             // 36864
#define AT_QOFF  (2 * AT_STAGE)            // 73728
#define AT_SMEM  (AT_QOFF + 2 * 128 * AT_STR)   // 110592

__global__ __launch_bounds__(256)
void attn_tc_kernel(const bf16* __restrict__ Qh, const bf16* __restrict__ Ql,
                    const bf16* __restrict__ Kh, const bf16* __restrict__ Kl,
                    const bf16* __restrict__ Vh, const bf16* __restrict__ Vl,
                    bf16* __restrict__ Ch, bf16* __restrict__ Cl)
{
    extern __shared__ char smem[];
    const uint32_t sb = smem_to_u32(smem);
    const int tid = threadIdx.x;
    const int wid = tid >> 5;
    const int lid = tid & 31;
    const int q0  = blockIdx.x * 128;
    const int h   = blockIdx.y;
    const int b   = blockIdx.z;
    const size_t ebase = ((size_t)b * S_) * D_ + (size_t)h * DK_;   // + s*1024 + d

    // ---- stage Q (hi at AT_QOFF, lo at +128*AT_STR) and K/V chunk 0 ----
    {
        // Q: 128 rows x 8 16B-chunks = 1024 per tile; 4 iters/thread/tile
#pragma unroll
        for (int l = 0; l < 4; l++) {
            int idx = tid + l * 256;
            int row = idx >> 3, c8 = idx & 7;
            size_t g = ebase + (size_t)(q0 + row) * 1024 + c8 * 8;
            uint32_t s = sb + AT_QOFF + (uint32_t)row * AT_STR + c8 * 16;
            CP_ASYNC16(s, Qh + g);
            CP_ASYNC16(s + 128 * AT_STR, Ql + g);
        }
        // K/V chunk 0 -> stage 0: 64 rows x 8 chunks = 512 per tile; 2 iters
#pragma unroll
        for (int l = 0; l < 2; l++) {
            int idx = tid + l * 256;
            int row = idx >> 3, c8 = idx & 7;
            size_t g = ebase + (size_t)row * 1024 + c8 * 8;
            uint32_t s = sb + (uint32_t)row * AT_STR + c8 * 16;
            CP_ASYNC16(s + 0 * AT_TILE, Kh + g);
            CP_ASYNC16(s + 1 * AT_TILE, Kl + g);
            CP_ASYNC16(s + 2 * AT_TILE, Vh + g);
            CP_ASYNC16(s + 3 * AT_TILE, Vl + g);
        }
        CP_COMMIT();
        CP_WAIT0();
        __syncthreads();
    }

    // ---- Q hi fragments to registers (m16 x k64 = 4 ksteps) ----
    const uint32_t qAddrBase = sb + AT_QOFF + (uint32_t)(wid * 16 + (lid & 15)) * AT_STR
                               + ((lid & 16) ? 16u : 0u);
    uint32_t qh[4][4];
#pragma unroll
    for (int ks = 0; ks < 4; ks++) ldsm4(qh[ks], qAddrBase + ks * 32);

    float m0 = -INFINITY, m1 = -INFINITY, l0 = 0.f, l1 = 0.f;
    float o[8][4];
#pragma unroll
    for (int dt = 0; dt < 8; dt++)
#pragma unroll
        for (int q = 0; q < 4; q++) o[dt][q] = 0.f;

    // precomputed lane components
    const uint32_t kRow = (uint32_t)((lid & 7) + ((lid & 16) ? 8 : 0)) * AT_STR + ((lid & 8) ? 16u : 0u);
    const uint32_t vRow = (uint32_t)(lid & 15) * AT_STR + ((lid & 16) ? 16u : 0u);

    for (int c = 0; c < 32; c++) {
        const uint32_t st = sb + (uint32_t)(c & 1) * AT_STAGE;

        // issue async loads for next chunk
        if (c + 1 < 32) {
            const uint32_t sn = sb + (uint32_t)((c + 1) & 1) * AT_STAGE;
            const int ks0 = (c + 1) * 64;
#pragma unroll
            for (int l = 0; l < 2; l++) {
                int idx = tid + l * 256;
                int row = idx >> 3, c8 = idx & 7;
                size_t g = ebase + (size_t)(ks0 + row) * 1024 + c8 * 8;
                uint32_t s = sn + (uint32_t)row * AT_STR + c8 * 16;
                CP_ASYNC16(s + 0 * AT_TILE, Kh + g);
                CP_ASYNC16(s + 1 * AT_TILE, Kl + g);
                CP_ASYNC16(s + 2 * AT_TILE, Vh + g);
                CP_ASYNC16(s + 3 * AT_TILE, Vl + g);
            }
            CP_COMMIT();
        }

        // ---- S = Q K^T (3 passes) ----
        float s4[8][4];
#pragma unroll
        for (int nt = 0; nt < 8; nt++)
#pragma unroll
            for (int q = 0; q < 4; q++) s4[nt][q] = 0.f;

#pragma unroll
        for (int ks = 0; ks < 4; ks++) {
            uint32_t bh[4][4], bl[4][4], qlr[4];
#pragma unroll
            for (int g = 0; g < 4; g++) {
                uint32_t a = st + (uint32_t)(16 * g) * AT_STR + kRow + ks * 32;
                ldsm4(bh[g], a);                 // Kh tile
                ldsm4(bl[g], a + AT_TILE);       // Kl tile
            }
            ldsm4(qlr, qAddrBase + 128 * AT_STR + ks * 32);
#pragma unroll
            for (int nt = 0; nt < 8; nt++) {
                mma_bf16(s4[nt], qh[ks], &bh[nt >> 1][(nt & 1) * 2]);
                mma_bf16(s4[nt], qh[ks], &bl[nt >> 1][(nt & 1) * 2]);
                mma_bf16(s4[nt], qlr,    &bh[nt >> 1][(nt & 1) * 2]);
            }
        }

        // ---- online softmax (rows r0 = lid>>2, r1 = r0+8) ----
        float mx0 = -INFINITY, mx1 = -INFINITY;
#pragma unroll
        for (int nt = 0; nt < 8; nt++) {
            mx0 = fmaxf(mx0, fmaxf(s4[nt][0], s4[nt][1]));
            mx1 = fmaxf(mx1, fmaxf(s4[nt][2], s4[nt][3]));
        }
        mx0 = fmaxf(mx0, __shfl_xor_sync(0xffffffffu, mx0, 1));
        mx0 = fmaxf(mx0, __shfl_xor_sync(0xffffffffu, mx0, 2));
        mx1 = fmaxf(mx1, __shfl_xor_sync(0xffffffffu, mx1, 1));
        mx1 = fmaxf(mx1, __shfl_xor_sync(0xffffffffu, mx1, 2));
        const float mn0 = fmaxf(m0, mx0), mn1 = fmaxf(m1, mx1);
        const float f0 = __expf(m0 - mn0), f1 = __expf(m1 - mn1);
        m0 = mn0; m1 = mn1;
        float sum0 = 0.f, sum1 = 0.f;
#pragma unroll
        for (int nt = 0; nt < 8; nt++) {
            s4[nt][0] = __expf(s4[nt][0] - mn0);
            s4[nt][1] = __expf(s4[nt][1] - mn0);
            s4[nt][2] = __expf(s4[nt][2] - mn1);
            s4[nt][3] = __expf(s4[nt][3] - mn1);
            sum0 += s4[nt][0] + s4[nt][1];
            sum1 += s4[nt][2] + s4[nt][3];
        }
        sum0 += __shfl_xor_sync(0xffffffffu, sum0, 1);
        sum0 += __shfl_xor_sync(0xffffffffu, sum0, 2);
        sum1 += __shfl_xor_sync(0xffffffffu, sum1, 1);
        sum1 += __shfl_xor_sync(0xffffffffu, sum1, 2);
        l0 = l0 * f0 + sum0;
        l1 = l1 * f1 + sum1;
#pragma unroll
        for (int dt = 0; dt < 8; dt++) {
            o[dt][0] *= f0; o[dt][1] *= f0; o[dt][2] *= f1; o[dt][3] *= f1;
        }

        // ---- pack P -> bf16 hi/lo A-fragments ----
        uint32_t ph[8][2], pl[8][2];
#pragma unroll
        for (int nt = 0; nt < 8; nt++) {
            bf16 h0 = __float2bfloat16(s4[nt][0]), h1 = __float2bfloat16(s4[nt][1]);
            bf16 h2 = __float2bfloat16(s4[nt][2]), h3 = __float2bfloat16(s4[nt][3]);
            ph[nt][0] = pack_bf16(__bfloat162float(h0), __bfloat162float(h1));
            ph[nt][1] = pack_bf16(__bfloat162float(h2), __bfloat162float(h3));
            pl[nt][0] = pack_bf16(s4[nt][0] - __bfloat162float(h0), s4[nt][1] - __bfloat162float(h1));
            pl[nt][1] = pack_bf16(s4[nt][2] - __bfloat162float(h2), s4[nt][3] - __bfloat162float(h3));
        }

        // ---- O += P V (3 passes), V^T via ldmatrix.trans ----
#pragma unroll
        for (int ks = 0; ks < 4; ks++) {
            uint32_t pa_h[4] = { ph[2 * ks][0], ph[2 * ks][1], ph[2 * ks + 1][0], ph[2 * ks + 1][1] };
            uint32_t pa_l[4] = { pl[2 * ks][0], pl[2 * ks][1], pl[2 * ks + 1][0], pl[2 * ks + 1][1] };
#pragma unroll
            for (int dp = 0; dp < 4; dp++) {
                uint32_t vh4[4], vl4[4];
                uint32_t a = st + 2 * AT_TILE + (uint32_t)(16 * ks) * AT_STR + vRow + dp * 32;
                ldsm4t(vh4, a);
                ldsm4t(vl4, a + AT_TILE);
                mma_bf16(o[2 * dp],     pa_h, &vh4[0]);
                mma_bf16(o[2 * dp + 1], pa_h, &vh4[2]);
                mma_bf16(o[2 * dp],     pa_h, &vl4[0]);
                mma_bf16(o[2 * dp + 1], pa_h, &vl4[2]);
                mma_bf16(o[2 * dp],     pa_l, &vh4[0]);
                mma_bf16(o[2 * dp + 1], pa_l, &vh4[2]);
            }
        }

        if (c + 1 < 32) CP_WAIT0();
        __syncthreads();
    }

    // ---- epilogue: normalize, split hi/lo, store ctx ----
    const float inv0 = 1.f / l0, inv1 = 1.f / l1;
    const int r0 = q0 + wid * 16 + (lid >> 2);
    const int cc = (lid & 3) * 2;
#pragma unroll
    for (int dt = 0; dt < 8; dt++) {
        float v0 = o[dt][0] * inv0, v1 = o[dt][1] * inv0;
        float v2 = o[dt][2] * inv1, v3 = o[dt][3] * inv1;
        bf16 h0 = __float2bfloat16(v0), h1 = __float2bfloat16(v1);
        bf16 h2 = __float2bfloat16(v2), h3 = __float2bfloat16(v3);
        size_t off0 = ebase + (size_t)r0 * 1024 + dt * 8 + cc;
        size_t off1 = ebase + (size_t)(r0 + 8) * 1024 + dt * 8 + cc;
        *(uint32_t*)&Ch[off0] = pack_bf16(__bfloat162float(h0), __bfloat162float(h1));
        *(uint32_t*)&Cl[off0] = pack_bf16(v0 - __bfloat162float(h0), v1 - __bfloat162float(h1));
        *(uint32_t*)&Ch[off1] = pack_bf16(__bfloat162float(h2), __bfloat162float(h3));
        *(uint32_t*)&Cl[off1] = pack_bf16(v2 - __bfloat162float(h2), v3 - __bfloat162float(h3));
    }
}

// ---------------------------------------------------------------------------
extern "C" void kernel_launch(void* const* d_in, const int* in_sizes, int n_in,
                              void* d_out, int out_size)
{
    const float* X  = (const float*)d_in[0];
    const float* Wq = (const float*)d_in[1];
    const float* Wk = (const float*)d_in[2];
    const float* Wv = (const float*)d_in[3];
    const float* Wo = (const float*)d_in[4];
    float* out = (float*)d_out;

    bf16 *Ah, *Al, *Wh, *Wl, *Qh, *Ql, *Kh, *Kl, *Vh, *Vl;
    cudaGetSymbolAddress((void**)&Ah, g_Ah);
    cudaGetSymbolAddress((void**)&Al, g_Al);
    cudaGetSymbolAddress((void**)&Wh, g_Wh);
    cudaGetSymbolAddress((void**)&Wl, g_Wl);
    cudaGetSymbolAddress((void**)&Qh, g_Qh);
    cudaGetSymbolAddress((void**)&Ql, g_Ql);
    cudaGetSymbolAddress((void**)&Kh, g_Kh);
    cudaGetSymbolAddress((void**)&Kl, g_Kl);
    cudaGetSymbolAddress((void**)&Vh, g_Vh);
    cudaGetSymbolAddress((void**)&Vl, g_Vl);

    cudaFuncSetAttribute(gemm_tc_kernel, cudaFuncAttributeMaxDynamicSharedMemorySize, GEMM_SMEM);
    cudaFuncSetAttribute(attn_tc_kernel, cudaFuncAttributeMaxDynamicSharedMemorySize, AT_SMEM);

    const int NX = MTOT * D_;
    const int NW = D_ * D_;

    // 0) hi/lo splits of X and weights
    cvt_hilo<<<NX / 256, 256>>>(X,  Ah, Al, NX);
    cvt_hilo<<<NW / 256, 256>>>(Wq, Wh + 0 * (size_t)NW, Wl + 0 * (size_t)NW, NW);
    cvt_hilo<<<NW / 256, 256>>>(Wk, Wh + 1 * (size_t)NW, Wl + 1 * (size_t)NW, NW);
    cvt_hilo<<<NW / 256, 256>>>(Wv, Wh + 2 * (size_t)NW, Wl + 2 * (size_t)NW, NW);
    cvt_hilo<<<NW / 256, 256>>>(Wo, Wh + 3 * (size_t)NW, Wl + 3 * (size_t)NW, NW);

    // 1) QKV projections -> bf16 hi/lo directly (Q pre-scaled by 0.125)
    dim3 gqkv(1024 / 128, MTOT / 128, 3);
    gemm_tc_kernel<<<gqkv, 512, GEMM_SMEM>>>(
        Ah, Al,
        Wh + 0 * (size_t)NW, Wl + 0 * (size_t)NW,
        Wh + 1 * (size_t)NW, Wl + 1 * (size_t)NW,
        Wh + 2 * (size_t)NW, Wl + 2 * (size_t)NW,
        Qh, Ql, Kh, Kl, Vh, Vl,
        nullptr, 0.125f);

    // 2) attention -> ctx hi/lo into Ah/Al (X split no longer needed)
    dim3 gattn(S_ / 128, H_, B_);
    attn_tc_kernel<<<gattn, 256, AT_SMEM>>>(Qh, Ql, Kh, Kl, Vh, Vl, Ah, Al);

    // 3) output projection -> fp32 out
    dim3 go(1024 / 128, MTOT / 128, 1);
    gemm_tc_kernel<<<go, 512, GEMM_SMEM>>>(
        Ah, Al,
        Wh + 3 * (size_t)NW, Wl + 3 * (size_t)NW,
        Wh + 3 * (size_t)NW, Wl + 3 * (size_t)NW,
        Wh + 3 * (size_t)NW, Wl + 3 * (size_t)NW,
        Qh, Ql, Qh, Ql, Qh, Ql,
        out, 1.f);
}

// round 8
// speedup vs baseline: 3.4919x; 1.0192x over previous
#include <cuda_runtime.h>
#include <cuda_bf16.h>
#include <math.h>
#include <cstdint>

#define B_  4
#define S_  2048
#define D_  1024
#define H_  16
#define DK_ 64
#define MTOT (B_*S_)   // 8192
#define NX_  (MTOT * D_)      // 8388608
#define NW_  (D_ * D_)        // 1048576

typedef __nv_bfloat16 bf16;

// ---------------------------------------------------------------------------
// Device-global scratch (allocation-free rule)
// ---------------------------------------------------------------------------
__device__ bf16 g_Ah[(size_t)NX_];   // hi(X), later hi(ctx)
__device__ bf16 g_Al[(size_t)NX_];   // lo(X), later lo(ctx)
__device__ bf16 g_Wh[4 * (size_t)NW_];
__device__ bf16 g_Wl[4 * (size_t)NW_];
__device__ bf16 g_Qh[(size_t)NX_];
__device__ bf16 g_Ql[(size_t)NX_];
__device__ bf16 g_Kh[(size_t)NX_];
__device__ bf16 g_Kl[(size_t)NX_];
__device__ bf16 g_Vh[(size_t)NX_];
__device__ bf16 g_Vl[(size_t)NX_];

__device__ __forceinline__ uint32_t smem_to_u32(const void* p) {
    uint32_t a;
    asm("{ .reg .u64 t; cvta.to.shared.u64 t, %1; cvt.u32.u64 %0, t; }" : "=r"(a) : "l"(p));
    return a;
}
__device__ __forceinline__ void ldsm4(uint32_t* r, uint32_t addr) {
    asm volatile("ldmatrix.sync.aligned.m8n8.x4.shared.b16 {%0,%1,%2,%3}, [%4];"
                 : "=r"(r[0]), "=r"(r[1]), "=r"(r[2]), "=r"(r[3]) : "r"(addr));
}
__device__ __forceinline__ void ldsm4t(uint32_t* r, uint32_t addr) {
    asm volatile("ldmatrix.sync.aligned.m8n8.x4.trans.shared.b16 {%0,%1,%2,%3}, [%4];"
                 : "=r"(r[0]), "=r"(r[1]), "=r"(r[2]), "=r"(r[3]) : "r"(addr));
}
__device__ __forceinline__ void mma_bf16(float* d, const uint32_t* a, const uint32_t* b) {
    asm volatile("mma.sync.aligned.m16n8k16.row.col.f32.bf16.bf16.f32 "
                 "{%0,%1,%2,%3}, {%4,%5,%6,%7}, {%8,%9}, {%0,%1,%2,%3};"
                 : "+f"(d[0]), "+f"(d[1]), "+f"(d[2]), "+f"(d[3])
                 : "r"(a[0]), "r"(a[1]), "r"(a[2]), "r"(a[3]), "r"(b[0]), "r"(b[1]));
}
#define CP_ASYNC16(s, g) \
    asm volatile("cp.async.cg.shared.global [%0], [%1], 16;" :: "r"(s), "l"(g))
#define CP_COMMIT()  asm volatile("cp.async.commit_group;" ::: "memory")
#define CP_WAIT0()   asm volatile("cp.async.wait_group 0;" ::: "memory")
#define CP_WAIT1()   asm volatile("cp.async.wait_group 1;" ::: "memory")

__device__ __forceinline__ uint32_t pack_bf16(float a, float b) {
    __nv_bfloat162 t = __floats2bfloat162_rn(a, b);
    return *(uint32_t*)&t;
}

// ---------------------------------------------------------------------------
// Fused fp32 -> (hi, lo) bf16 split for X and all 4 weights (one launch)
// ---------------------------------------------------------------------------
__global__ void cvt_all(const float* __restrict__ X,  const float* __restrict__ Wq,
                        const float* __restrict__ Wk, const float* __restrict__ Wv,
                        const float* __restrict__ Wo,
                        bf16* __restrict__ Ah, bf16* __restrict__ Al,
                        bf16* __restrict__ Wh, bf16* __restrict__ Wl)
{
    size_t i = (size_t)blockIdx.x * 256 + threadIdx.x;
    const float* src; bf16 *h, *l; size_t off;
    if (i < (size_t)NX_) {
        src = X; h = Ah; l = Al; off = i;
    } else {
        size_t j = i - NX_;
        int w = (int)(j >> 20);          // NW_ = 1<<20
        off = j & (NW_ - 1);
        src = (w == 0) ? Wq : (w == 1) ? Wk : (w == 2) ? Wv : Wo;
        h = Wh + (size_t)w * NW_;
        l = Wl + (size_t)w * NW_;
    }
    float v = src[off];
    bf16 hh = __float2bfloat16(v);
    h[off] = hh;
    l[off] = __float2bfloat16(v - __bfloat162float(hh));
}

// ---------------------------------------------------------------------------
// bf16x3 GEMM on mma.sync: Y = X @ W^T. CTA 128x128, 512 thr, K-chunk 32,
// 3-stage cp.async pipeline. Epilogue: fp32 OR hi/lo bf16 split (+scale).
// ---------------------------------------------------------------------------
#define KC        32
#define TSTRIDE   40
#define TILE_B    (128 * TSTRIDE * 2)       // 10240
#define STAGE_B   (4 * TILE_B)              // 40960
#define NSTAGE    3
#define GEMM_SMEM (NSTAGE * STAGE_B)        // 122880

__global__ __launch_bounds__(512, 1)
void gemm_tc_kernel(const bf16* __restrict__ Ah, const bf16* __restrict__ Al,
                    const bf16* __restrict__ B0h, const bf16* __restrict__ B0l,
                    const bf16* __restrict__ B1h, const bf16* __restrict__ B1l,
                    const bf16* __restrict__ B2h, const bf16* __restrict__ B2l,
                    bf16* __restrict__ Yh0, bf16* __restrict__ Yl0,
                    bf16* __restrict__ Yh1, bf16* __restrict__ Yl1,
                    bf16* __restrict__ Yh2, bf16* __restrict__ Yl2,
                    float* __restrict__ Yf, float sc0)
{
    const bf16* Bh = (blockIdx.z == 0) ? B0h : (blockIdx.z == 1) ? B1h : B2h;
    const bf16* Bl = (blockIdx.z == 0) ? B0l : (blockIdx.z == 1) ? B1l : B2l;
    bf16* Yh = (blockIdx.z == 0) ? Yh0 : (blockIdx.z == 1) ? Yh1 : Yh2;
    bf16* Yl = (blockIdx.z == 0) ? Yl0 : (blockIdx.z == 1) ? Yl1 : Yl2;
    const float osc = (blockIdx.z == 0) ? sc0 : 1.f;

    extern __shared__ char smem[];
    const uint32_t sb = smem_to_u32(smem);
    const int tid = threadIdx.x;
    const int wid = tid >> 5;
    const int lid = tid & 31;
    const int wm  = wid >> 2;
    const int wn  = wid & 3;
    const int m0  = blockIdx.y * 128;
    const int n0  = blockIdx.x * 128;

    const int grow = tid >> 2;
    const uint32_t s_off = (uint32_t)grow * (TSTRIDE * 2) + (uint32_t)(tid & 3) * 16;
    const size_t gA = (size_t)(m0 + grow) * 1024 + (tid & 3) * 8;
    const size_t gB = (size_t)(n0 + grow) * 1024 + (tid & 3) * 8;

    const uint32_t aRow = (uint32_t)(wm * 32 + (lid & 15)) * (TSTRIDE * 2) + ((lid & 16) ? 16u : 0u);
    const uint32_t bRow = (uint32_t)(wn * 32 + (lid & 7) + ((lid & 16) ? 8 : 0)) * (TSTRIDE * 2)
                          + ((lid & 8) ? 16u : 0u);

    float acc[2][4][4];
#pragma unroll
    for (int mb = 0; mb < 2; mb++)
#pragma unroll
        for (int nb = 0; nb < 4; nb++)
#pragma unroll
            for (int q = 0; q < 4; q++) acc[mb][nb][q] = 0.f;

    // issue one chunk into a stage
    auto issue = [&](int stage, int c) {
        const uint32_t st = sb + (uint32_t)stage * STAGE_B + s_off;
        const size_t ko = (size_t)c * KC;
        CP_ASYNC16(st + 0 * TILE_B, Ah + gA + ko);
        CP_ASYNC16(st + 1 * TILE_B, Al + gA + ko);
        CP_ASYNC16(st + 2 * TILE_B, Bh + gB + ko);
        CP_ASYNC16(st + 3 * TILE_B, Bl + gB + ko);
    };

    issue(0, 0); CP_COMMIT();
    issue(1, 1); CP_COMMIT();

    int stage = 0, nstage = 2;
    for (int c = 0; c < 32; c++) {
        if (c < 30) CP_WAIT1(); else CP_WAIT0();
        __syncthreads();
        if (c + 2 < 32) {
            issue(nstage, c + 2); CP_COMMIT();
            if (++nstage == NSTAGE) nstage = 0;
        }

        const uint32_t st = sb + (uint32_t)stage * STAGE_B;
#pragma unroll
        for (int ks = 0; ks < 2; ks++) {
            const uint32_t kb = (uint32_t)ks * 32;
            uint32_t fa[2][4], fb_h[2][4], fb_l[2][4], fal[2][4];
#pragma unroll
            for (int mb = 0; mb < 2; mb++)
                ldsm4(fa[mb], st + 0 * TILE_B + aRow + (uint32_t)mb * (16 * TSTRIDE * 2) + kb);
#pragma unroll
            for (int nb = 0; nb < 2; nb++) {
                ldsm4(fb_h[nb], st + 2 * TILE_B + bRow + (uint32_t)nb * (16 * TSTRIDE * 2) + kb);
                ldsm4(fb_l[nb], st + 3 * TILE_B + bRow + (uint32_t)nb * (16 * TSTRIDE * 2) + kb);
            }
#pragma unroll
            for (int mb = 0; mb < 2; mb++)
#pragma unroll
                for (int nb = 0; nb < 4; nb++) {
                    mma_bf16(acc[mb][nb], fa[mb], &fb_h[nb >> 1][(nb & 1) * 2]);
                    mma_bf16(acc[mb][nb], fa[mb], &fb_l[nb >> 1][(nb & 1) * 2]);
                }
#pragma unroll
            for (int mb = 0; mb < 2; mb++)
                ldsm4(fal[mb], st + 1 * TILE_B + aRow + (uint32_t)mb * (16 * TSTRIDE * 2) + kb);
#pragma unroll
            for (int mb = 0; mb < 2; mb++)
#pragma unroll
                for (int nb = 0; nb < 4; nb++)
                    mma_bf16(acc[mb][nb], fal[mb], &fb_h[nb >> 1][(nb & 1) * 2]);
        }
        if (++stage == NSTAGE) stage = 0;
    }

    const int rr = lid >> 2;
    const int cc = (lid & 3) * 2;
    if (Yf) {
#pragma unroll
        for (int mb = 0; mb < 2; mb++) {
            const int row = m0 + wm * 32 + mb * 16 + rr;
#pragma unroll
            for (int nb = 0; nb < 4; nb++) {
                const int col = n0 + wn * 32 + nb * 8 + cc;
                *(float2*)&Yf[(size_t)row * 1024 + col]       = make_float2(acc[mb][nb][0], acc[mb][nb][1]);
                *(float2*)&Yf[(size_t)(row + 8) * 1024 + col] = make_float2(acc[mb][nb][2], acc[mb][nb][3]);
            }
        }
    } else {
#pragma unroll
        for (int mb = 0; mb < 2; mb++) {
            const int row = m0 + wm * 32 + mb * 16 + rr;
#pragma unroll
            for (int nb = 0; nb < 4; nb++) {
                const int col = n0 + wn * 32 + nb * 8 + cc;
#pragma unroll
                for (int half = 0; half < 2; half++) {
                    float v0 = acc[mb][nb][half * 2 + 0] * osc;
                    float v1 = acc[mb][nb][half * 2 + 1] * osc;
                    bf16 h0 = __float2bfloat16(v0), h1 = __float2bfloat16(v1);
                    float l0 = v0 - __bfloat162float(h0), l1 = v1 - __bfloat162float(h1);
                    size_t off = (size_t)(row + half * 8) * 1024 + col;
                    *(uint32_t*)&Yh[off] = pack_bf16(__bfloat162float(h0), __bfloat162float(h1));
                    *(uint32_t*)&Yl[off] = pack_bf16(l0, l1);
                }
            }
        }
    }
}

// ---------------------------------------------------------------------------
// Flash attention on mma.sync bf16x3 (unchanged from passing R7 kernel)
// ---------------------------------------------------------------------------
#define AT_STR   144
#define AT_TILE  (64 * AT_STR)
#define AT_STAGE (4 * AT_TILE)
#define AT_QOFF  (2 * AT_STAGE)
#define AT_SMEM  (AT_QOFF + 2 * 128 * AT_STR)   // 110592

__global__ __launch_bounds__(256)
void attn_tc_kernel(const bf16* __restrict__ Qh, const bf16* __restrict__ Ql,
                    const bf16* __restrict__ Kh, const bf16* __restrict__ Kl,
                    const bf16* __restrict__ Vh, const bf16* __restrict__ Vl,
                    bf16* __restrict__ Ch, bf16* __restrict__ Cl)
{
    extern __shared__ char smem[];
    const uint32_t sb = smem_to_u32(smem);
    const int tid = threadIdx.x;
    const int wid = tid >> 5;
    const int lid = tid & 31;
    const int q0  = blockIdx.x * 128;
    const int h   = blockIdx.y;
    const int b   = blockIdx.z;
    const size_t ebase = ((size_t)b * S_) * D_ + (size_t)h * DK_;

    {
#pragma unroll
        for (int l = 0; l < 4; l++) {
            int idx = tid + l * 256;
            int row = idx >> 3, c8 = idx & 7;
            size_t g = ebase + (size_t)(q0 + row) * 1024 + c8 * 8;
            uint32_t s = sb + AT_QOFF + (uint32_t)row * AT_STR + c8 * 16;
            CP_ASYNC16(s, Qh + g);
            CP_ASYNC16(s + 128 * AT_STR, Ql + g);
        }
#pragma unroll
        for (int l = 0; l < 2; l++) {
            int idx = tid + l * 256;
            int row = idx >> 3, c8 = idx & 7;
            size_t g = ebase + (size_t)row * 1024 + c8 * 8;
            uint32_t s = sb + (uint32_t)row * AT_STR + c8 * 16;
            CP_ASYNC16(s + 0 * AT_TILE, Kh + g);
            CP_ASYNC16(s + 1 * AT_TILE, Kl + g);
            CP_ASYNC16(s + 2 * AT_TILE, Vh + g);
            CP_ASYNC16(s + 3 * AT_TILE, Vl + g);
        }
        CP_COMMIT();
        CP_WAIT0();
        __syncthreads();
    }

    const uint32_t qAddrBase = sb + AT_QOFF + (uint32_t)(wid * 16 + (lid & 15)) * AT_STR
                               + ((lid & 16) ? 16u : 0u);
    uint32_t qh[4][4];
#pragma unroll
    for (int ks = 0; ks < 4; ks++) ldsm4(qh[ks], qAddrBase + ks * 32);

    float m0 = -INFINITY, m1 = -INFINITY, l0 = 0.f, l1 = 0.f;
    float o[8][4];
#pragma unroll
    for (int dt = 0; dt < 8; dt++)
#pragma unroll
        for (int q = 0; q < 4; q++) o[dt][q] = 0.f;

    const uint32_t kRow = (uint32_t)((lid & 7) + ((lid & 16) ? 8 : 0)) * AT_STR + ((lid & 8) ? 16u : 0u);
    const uint32_t vRow = (uint32_t)(lid & 15) * AT_STR + ((lid & 16) ? 16u : 0u);

    for (int c = 0; c < 32; c++) {
        const uint32_t st = sb + (uint32_t)(c & 1) * AT_STAGE;

        if (c + 1 < 32) {
            const uint32_t sn = sb + (uint32_t)((c + 1) & 1) * AT_STAGE;
            const int ks0 = (c + 1) * 64;
#pragma unroll
            for (int l = 0; l < 2; l++) {
                int idx = tid + l * 256;
                int row = idx >> 3, c8 = idx & 7;
                size_t g = ebase + (size_t)(ks0 + row) * 1024 + c8 * 8;
                uint32_t s = sn + (uint32_t)row * AT_STR + c8 * 16;
                CP_ASYNC16(s + 0 * AT_TILE, Kh + g);
                CP_ASYNC16(s + 1 * AT_TILE, Kl + g);
                CP_ASYNC16(s + 2 * AT_TILE, Vh + g);
                CP_ASYNC16(s + 3 * AT_TILE, Vl + g);
            }
            CP_COMMIT();
        }

        float s4[8][4];
#pragma unroll
        for (int nt = 0; nt < 8; nt++)
#pragma unroll
            for (int q = 0; q < 4; q++) s4[nt][q] = 0.f;

#pragma unroll
        for (int ks = 0; ks < 4; ks++) {
            uint32_t bh[4][4], bl[4][4], qlr[4];
#pragma unroll
            for (int g = 0; g < 4; g++) {
                uint32_t a = st + (uint32_t)(16 * g) * AT_STR + kRow + ks * 32;
                ldsm4(bh[g], a);
                ldsm4(bl[g], a + AT_TILE);
            }
            ldsm4(qlr, qAddrBase + 128 * AT_STR + ks * 32);
#pragma unroll
            for (int nt = 0; nt < 8; nt++) {
                mma_bf16(s4[nt], qh[ks], &bh[nt >> 1][(nt & 1) * 2]);
                mma_bf16(s4[nt], qh[ks], &bl[nt >> 1][(nt & 1) * 2]);
                mma_bf16(s4[nt], qlr,    &bh[nt >> 1][(nt & 1) * 2]);
            }
        }

        float mx0 = -INFINITY, mx1 = -INFINITY;
#pragma unroll
        for (int nt = 0; nt < 8; nt++) {
            mx0 = fmaxf(mx0, fmaxf(s4[nt][0], s4[nt][1]));
            mx1 = fmaxf(mx1, fmaxf(s4[nt][2], s4[nt][3]));
        }
        mx0 = fmaxf(mx0, __shfl_xor_sync(0xffffffffu, mx0, 1));
        mx0 = fmaxf(mx0, __shfl_xor_sync(0xffffffffu, mx0, 2));
        mx1 = fmaxf(mx1, __shfl_xor_sync(0xffffffffu, mx1, 1));
        mx1 = fmaxf(mx1, __shfl_xor_sync(0xffffffffu, mx1, 2));
        const float mn0 = fmaxf(m0, mx0), mn1 = fmaxf(m1, mx1);
        const float f0 = __expf(m0 - mn0), f1 = __expf(m1 - mn1);
        m0 = mn0; m1 = mn1;
        float sum0 = 0.f, sum1 = 0.f;
#pragma unroll
        for (int nt = 0; nt < 8; nt++) {
            s4[nt][0] = __expf(s4[nt][0] - mn0);
            s4[nt][1] = __expf(s4[nt][1] - mn0);
            s4[nt][2] = __expf(s4[nt][2] - mn1);
            s4[nt][3] = __expf(s4[nt][3] - mn1);
            sum0 += s4[nt][0] + s4[nt][1];
            sum1 += s4[nt][2] + s4[nt][3];
        }
        sum0 += __shfl_xor_sync(0xffffffffu, sum0, 1);
        sum0 += __shfl_xor_sync(0xffffffffu, sum0, 2);
        sum1 += __shfl_xor_sync(0xffffffffu, sum1, 1);
        sum1 += __shfl_xor_sync(0xffffffffu, sum1, 2);
        l0 = l0 * f0 + sum0;
        l1 = l1 * f1 + sum1;
#pragma unroll
        for (int dt = 0; dt < 8; dt++) {
            o[dt][0] *= f0; o[dt][1] *= f0; o[dt][2] *= f1; o[dt][3] *= f1;
        }

        uint32_t ph[8][2], pl[8][2];
#pragma unroll
        for (int nt = 0; nt < 8; nt++) {
            bf16 h0 = __float2bfloat16(s4[nt][0]), h1 = __float2bfloat16(s4[nt][1]);
            bf16 h2 = __float2bfloat16(s4[nt][2]), h3 = __float2bfloat16(s4[nt][3]);
            ph[nt][0] = pack_bf16(__bfloat162float(h0), __bfloat162float(h1));
            ph[nt][1] = pack_bf16(__bfloat162float(h2), __bfloat162float(h3));
            pl[nt][0] = pack_bf16(s4[nt][0] - __bfloat162float(h0), s4[nt][1] - __bfloat162float(h1));
            pl[nt][1] = pack_bf16(s4[nt][2] - __bfloat162float(h2), s4[nt][3] - __bfloat162float(h3));
        }

#pragma unroll
        for (int ks = 0; ks < 4; ks++) {
            uint32_t pa_h[4] = { ph[2 * ks][0], ph[2 * ks][1], ph[2 * ks + 1][0], ph[2 * ks + 1][1] };
            uint32_t pa_l[4] = { pl[2 * ks][0], pl[2 * ks][1], pl[2 * ks + 1][0], pl[2 * ks + 1][1] };
#pragma unroll
            for (int dp = 0; dp < 4; dp++) {
                uint32_t vh4[4], vl4[4];
                uint32_t a = st + 2 * AT_TILE + (uint32_t)(16 * ks) * AT_STR + vRow + dp * 32;
                ldsm4t(vh4, a);
                ldsm4t(vl4, a + AT_TILE);
                mma_bf16(o[2 * dp],     pa_h, &vh4[0]);
                mma_bf16(o[2 * dp + 1], pa_h, &vh4[2]);
                mma_bf16(o[2 * dp],     pa_h, &vl4[0]);
                mma_bf16(o[2 * dp + 1], pa_h, &vl4[2]);
                mma_bf16(o[2 * dp],     pa_l, &vh4[0]);
                mma_bf16(o[2 * dp + 1], pa_l, &vh4[2]);
            }
        }

        if (c + 1 < 32) CP_WAIT0();
        __syncthreads();
    }

    const float inv0 = 1.f / l0, inv1 = 1.f / l1;
    const int r0 = q0 + wid * 16 + (lid >> 2);
    const int cc = (lid & 3) * 2;
#pragma unroll
    for (int dt = 0; dt < 8; dt++) {
        float v0 = o[dt][0] * inv0, v1 = o[dt][1] * inv0;
        float v2 = o[dt][2] * inv1, v3 = o[dt][3] * inv1;
        bf16 h0 = __float2bfloat16(v0), h1 = __float2bfloat16(v1);
        bf16 h2 = __float2bfloat16(v2), h3 = __float2bfloat16(v3);
        size_t off0 = ebase + (size_t)r0 * 1024 + dt * 8 + cc;
        size_t off1 = ebase + (size_t)(r0 + 8) * 1024 + dt * 8 + cc;
        *(uint32_t*)&Ch[off0] = pack_bf16(__bfloat162float(h0), __bfloat162float(h1));
        *(uint32_t*)&Cl[off0] = pack_bf16(v0 - __bfloat162float(h0), v1 - __bfloat162float(h1));
        *(uint32_t*)&Ch[off1] = pack_bf16(__bfloat162float(h2), __bfloat162float(h3));
        *(uint32_t*)&Cl[off1] = pack_bf16(v2 - __bfloat162float(h2), v3 - __bfloat162float(h3));
    }
}

// ---------------------------------------------------------------------------
extern "C" void kernel_launch(void* const* d_in, const int* in_sizes, int n_in,
                              void* d_out, int out_size)
{
    const float* X  = (const float*)d_in[0];
    const float* Wq = (const float*)d_in[1];
    const float* Wk = (const float*)d_in[2];
    const float* Wv = (const float*)d_in[3];
    const float* Wo = (const float*)d_in[4];
    float* out = (float*)d_out;

    bf16 *Ah, *Al, *Wh, *Wl, *Qh, *Ql, *Kh, *Kl, *Vh, *Vl;
    cudaGetSymbolAddress((void**)&Ah, g_Ah);
    cudaGetSymbolAddress((void**)&Al, g_Al);
    cudaGetSymbolAddress((void**)&Wh, g_Wh);
    cudaGetSymbolAddress((void**)&Wl, g_Wl);
    cudaGetSymbolAddress((void**)&Qh, g_Qh);
    cudaGetSymbolAddress((void**)&Ql, g_Ql);
    cudaGetSymbolAddress((void**)&Kh, g_Kh);
    cudaGetSymbolAddress((void**)&Kl, g_Kl);
    cudaGetSymbolAddress((void**)&Vh, g_Vh);
    cudaGetSymbolAddress((void**)&Vl, g_Vl);

    cudaFuncSetAttribute(gemm_tc_kernel, cudaFuncAttributeMaxDynamicSharedMemorySize, GEMM_SMEM);
    cudaFuncSetAttribute(attn_tc_kernel, cudaFuncAttributeMaxDynamicSharedMemorySize, AT_SMEM);

    // 0) one fused hi/lo split launch (X + 4 weights)
    const int totalBlocks = (NX_ + 4 * NW_) / 256;   // 49152
    cvt_all<<<totalBlocks, 256>>>(X, Wq, Wk, Wv, Wo, Ah, Al, Wh, Wl);

    // 1) QKV projections -> bf16 hi/lo (Q pre-scaled by 0.125)
    dim3 gqkv(1024 / 128, MTOT / 128, 3);
    gemm_tc_kernel<<<gqkv, 512, GEMM_SMEM>>>(
        Ah, Al,
        Wh + 0 * (size_t)NW_, Wl + 0 * (size_t)NW_,
        Wh + 1 * (size_t)NW_, Wl + 1 * (size_t)NW_,
        Wh + 2 * (size_t)NW_, Wl + 2 * (size_t)NW_,
        Qh, Ql, Kh, Kl, Vh, Vl,
        nullptr, 0.125f);

    // 2) attention -> ctx hi/lo into Ah/Al
    dim3 gattn(S_ / 128, H_, B_);
    attn_tc_kernel<<<gattn, 256, AT_SMEM>>>(Qh, Ql, Kh, Kl, Vh, Vl, Ah, Al);

    // 3) output projection -> fp32 out
    dim3 go(1024 / 128, MTOT / 128, 1);
    gemm_tc_kernel<<<go, 512, GEMM_SMEM>>>(
        Ah, Al,
        Wh + 3 * (size_t)NW_, Wl + 3 * (size_t)NW_,
        Wh + 3 * (size_t)NW_, Wl + 3 * (size_t)NW_,
        Wh + 3 * (size_t)NW_, Wl + 3 * (size_t)NW_,
        Qh, Ql, Qh, Ql, Qh, Ql,
        out, 1.f);
}